// round 12
// baseline (speedup 1.0000x reference)
#include <cuda_runtime.h>
#include <cuda_fp16.h>
#include <cstdint>

#define NNODES_MAX 100000
#define EDGES_MAX  1600000
#define DH 128
#define NGRAPH 512

// smem layout for layer kernel: As[128][136] + Ws[128][136] halfs
#define LK_STRIDE 136
#define LK_SMEM_BYTES (2 * 128 * LK_STRIDE * 2)

// ---------------- scratch (static device globals; no allocation) ------------
__device__ __half g_x16[NNODES_MAX * DH];    // input features, fp16
__device__ __half g_hA[NNODES_MAX * DH];     // layer-0 output
__device__ __half g_hB[NNODES_MAX * DH];     // layer-1 output
__device__ float  g_pool[NGRAPH * DH];       // per-graph sums (fp32)
__device__ float  g_cnt[NGRAPH];             // per-graph node counts
__device__ int    g_deg[NNODES_MAX];
__device__ int    g_cur[NNODES_MAX];
__device__ int    g_rowptr[NNODES_MAX + 1];
__device__ int    g_col[EDGES_MAX];

// ---------------- helpers ---------------------------------------------------
__device__ __forceinline__ void red2(float* p, float a, float b) {
    asm volatile("red.global.add.v2.f32 [%0], {%1,%2};"
                 :: "l"(p), "f"(a), "f"(b) : "memory");
}
__device__ __forceinline__ float4 h4_to_f4(uint2 u) {
    float2 fa = __half22float2(*reinterpret_cast<__half2*>(&u.x));
    float2 fb = __half22float2(*reinterpret_cast<__half2*>(&u.y));
    return make_float4(fa.x, fa.y, fb.x, fb.y);
}

// ---------------- init: zero pool/cnt/deg ------------------------------------
__global__ void init_kernel(int n) {
    int i = blockIdx.x * blockDim.x + threadIdx.x;
    if (i < NGRAPH * DH) g_pool[i] = 0.f;
    if (i < NGRAPH) g_cnt[i] = 0.f;
    if (i < n) g_deg[i] = 0;
}

// fused: degree histogram (over E) + per-graph node counts (over N)
__global__ void hist_count_kernel(const int* __restrict__ ei,
                                  const int* __restrict__ batch, int E, int N) {
    int i = blockIdx.x * blockDim.x + threadIdx.x;
    if (i < E) atomicAdd(&g_deg[ei[E + i]], 1);   // dst
    if (i < N) atomicAdd(&g_cnt[batch[i]], 1.0f);
}

// single-block exclusive scan of g_deg into g_rowptr; also seeds g_cur
__global__ void scan_kernel(int n) {
    const int T = 1024;
    __shared__ int part[T];
    int t = threadIdx.x;
    int C = (n + T - 1) / T;
    int beg = t * C;
    int end = beg + C < n ? beg + C : n;
    int s = 0;
    for (int i = beg; i < end; i++) s += g_deg[i];
    part[t] = s;
    __syncthreads();
    for (int off = 1; off < T; off <<= 1) {
        int v = (t >= off) ? part[t - off] : 0;
        __syncthreads();
        part[t] += v;
        __syncthreads();
    }
    int run = (t == 0) ? 0 : part[t - 1];
    for (int i = beg; i < end; i++) {
        g_rowptr[i] = run;
        g_cur[i]    = run;
        run += g_deg[i];
    }
    if (t == 0) g_rowptr[n] = part[T - 1];
}

__global__ void fill_kernel(const int* __restrict__ ei, int E) {
    int i = blockIdx.x * blockDim.x + threadIdx.x;
    if (i >= E) return;
    int s = ei[i];
    int d = ei[E + i];
    int pos = atomicAdd(&g_cur[d], 1);
    g_col[pos] = s;
}

// ---------------- converter (x only; W converted inline in layer kernel) -----
__global__ void convert_x_kernel(const float4* __restrict__ x, int n4) {
    int i = blockIdx.x * blockDim.x + threadIdx.x;
    if (i >= n4) return;
    float4 v = x[i];
    __half2* dst = reinterpret_cast<__half2*>(g_x16);
    dst[i * 2]     = __floats2half2_rn(v.x, v.y);
    dst[i * 2 + 1] = __floats2half2_rn(v.z, v.w);
}

// ---------------- fused layer: gather (R7 form) + HGEMM ----------------------
// Block owns 128 rows. Phase 1: stage W fp32->fp16 into Ws. Phase 2: 8 warps x
// 16 nodes gather (serial shfl, fp32 accum) directly into As. Phase 3: mma.
// src and dsth MUST NOT alias (double-buffered by caller).
template<bool RELU, bool POOL>
__global__ __launch_bounds__(256)
void layer_kernel(const __half* __restrict__ src, __half* __restrict__ dsth,
                  const float* __restrict__ Wf, const float* __restrict__ bias,
                  const int* __restrict__ batch, int N) {
    extern __shared__ __half smem[];
    __half* As = smem;                      // [128][LK_STRIDE]
    __half* Ws = smem + 128 * LK_STRIDE;    // [128][LK_STRIDE]

    const int tid  = threadIdx.x;
    const int wid  = tid >> 5;
    const int lane = tid & 31;
    const int rowBase = blockIdx.x * 128;

    // ---- phase 1: stage W[128][128] fp32 -> fp16 smem ----
#pragma unroll
    for (int t = 0; t < 8; t++) {
        int idx = tid + t * 256;        // 0..2047 = 128 rows x 16 chunks
        int row = idx >> 4;
        int ch  = (idx & 15) * 8;
        float4 wa = *reinterpret_cast<const float4*>(&Wf[row * DH + ch]);
        float4 wb = *reinterpret_cast<const float4*>(&Wf[row * DH + ch + 4]);
        uint4 o;
        *reinterpret_cast<__half2*>(&o.x) = __floats2half2_rn(wa.x, wa.y);
        *reinterpret_cast<__half2*>(&o.y) = __floats2half2_rn(wa.z, wa.w);
        *reinterpret_cast<__half2*>(&o.z) = __floats2half2_rn(wb.x, wb.y);
        *reinterpret_cast<__half2*>(&o.w) = __floats2half2_rn(wb.z, wb.w);
        *reinterpret_cast<uint4*>(&Ws[row * LK_STRIDE + ch]) = o;
    }

    // ---- phase 2: gather 16 nodes per warp into As (R7-proven loop) ----
    {
        const uint2* __restrict__ src2 = reinterpret_cast<const uint2*>(src);
        const int node0 = rowBase + wid * 16;
        for (int i = 0; i < 16; i++) {
            int node = node0 + i;
            if (node >= N) node = N - 1;       // duplicate row, epilogue-guarded
            const int beg = g_rowptr[node];
            const int end = g_rowptr[node + 1];
            float4 acc = h4_to_f4(src2[node * 32 + lane]);   // seed: own feats
            for (int base = beg; base < end; base += 32) {
                int idx = (base + lane < end) ? g_col[base + lane] : 0;
                int cnt = end - base; if (cnt > 32) cnt = 32;
#pragma unroll 4
                for (int j = 0; j < cnt; j++) {
                    int s = __shfl_sync(0xffffffffu, idx, j);
                    float4 v = h4_to_f4(src2[s * 32 + lane]);
                    acc.x += v.x; acc.y += v.y; acc.z += v.z; acc.w += v.w;
                }
            }
            uint2 o;
            *reinterpret_cast<__half2*>(&o.x) = __floats2half2_rn(acc.x, acc.y);
            *reinterpret_cast<__half2*>(&o.y) = __floats2half2_rn(acc.z, acc.w);
            *reinterpret_cast<uint2*>(&As[(wid * 16 + i) * LK_STRIDE + lane * 4]) = o;
        }
    }
    __syncthreads();

    // ---- phase 3: mma mainloop (R8-validated fragment mappings) ----
    const int g    = lane >> 2;
    const int c    = (lane & 3) * 2;
    const int mrow = (wid & 1) * 64;
    const int ncol = (wid >> 1) * 32;

    float acc[4][4][4];
#pragma unroll
    for (int mt = 0; mt < 4; mt++)
#pragma unroll
        for (int nt = 0; nt < 4; nt++)
#pragma unroll
            for (int q = 0; q < 4; q++) acc[mt][nt][q] = 0.f;

#pragma unroll
    for (int kk = 0; kk < 8; kk++) {
        const int k0 = kk * 16;
        uint32_t af[4][4], bf[4][2];
#pragma unroll
        for (int mt = 0; mt < 4; mt++) {
            uint32_t aaddr = (uint32_t)__cvta_generic_to_shared(
                &As[(mrow + mt * 16 + (lane & 15)) * LK_STRIDE + k0 + ((lane >> 4) << 3)]);
            asm volatile(
                "ldmatrix.sync.aligned.m8n8.x4.shared.b16 {%0,%1,%2,%3}, [%4];"
                : "=r"(af[mt][0]), "=r"(af[mt][1]),
                  "=r"(af[mt][2]), "=r"(af[mt][3])
                : "r"(aaddr));
        }
#pragma unroll
        for (int nt = 0; nt < 4; nt++) {
            uint32_t baddr = (uint32_t)__cvta_generic_to_shared(
                &Ws[(ncol + nt * 8 + (lane & 7)) * LK_STRIDE + k0 + (((lane >> 3) & 1) << 3)]);
            asm volatile(
                "ldmatrix.sync.aligned.m8n8.x2.shared.b16 {%0,%1}, [%2];"
                : "=r"(bf[nt][0]), "=r"(bf[nt][1])
                : "r"(baddr));
        }
#pragma unroll
        for (int mt = 0; mt < 4; mt++)
#pragma unroll
            for (int nt = 0; nt < 4; nt++) {
                asm volatile(
                    "mma.sync.aligned.m16n8k16.row.col.f32.f16.f16.f32 "
                    "{%0,%1,%2,%3}, {%4,%5,%6,%7}, {%8,%9}, {%0,%1,%2,%3};"
                    : "+f"(acc[mt][nt][0]), "+f"(acc[mt][nt][1]),
                      "+f"(acc[mt][nt][2]), "+f"(acc[mt][nt][3])
                    : "r"(af[mt][0]), "r"(af[mt][1]), "r"(af[mt][2]), "r"(af[mt][3]),
                      "r"(bf[nt][0]), "r"(bf[nt][1]));
            }
    }

    // ---- epilogue ----
#pragma unroll
    for (int nt = 0; nt < 4; nt++) {
        int col = ncol + nt * 8 + c;
        float2 bb = *reinterpret_cast<const float2*>(&bias[col]);
#pragma unroll
        for (int mt = 0; mt < 4; mt++) {
            int row0 = rowBase + mrow + mt * 16 + g;
            int row1 = row0 + 8;
            float c0 = acc[mt][nt][0] + bb.x;
            float c1 = acc[mt][nt][1] + bb.y;
            float c2 = acc[mt][nt][2] + bb.x;
            float c3 = acc[mt][nt][3] + bb.y;
            if (RELU) {
                c0 = fmaxf(c0, 0.f); c1 = fmaxf(c1, 0.f);
                c2 = fmaxf(c2, 0.f); c3 = fmaxf(c3, 0.f);
            }
            if (POOL) {
                if (row0 < N) red2(&g_pool[batch[row0] * DH + col], c0, c1);
                if (row1 < N) red2(&g_pool[batch[row1] * DH + col], c2, c3);
            } else {
                if (row0 < N)
                    *reinterpret_cast<__half2*>(&dsth[row0 * DH + col]) =
                        __floats2half2_rn(c0, c1);
                if (row1 < N)
                    *reinterpret_cast<__half2*>(&dsth[row1 * DH + col]) =
                        __floats2half2_rn(c2, c3);
            }
        }
    }
}

// ---------------- head: out[g][o] = dot(pool[g]/cnt[g], Wg[o]) + bg[o] ------
__global__ void final_kernel(const float* __restrict__ Wg,
                             const float* __restrict__ bg,
                             float* __restrict__ out) {
    int g = blockIdx.x;
    int lane = threadIdx.x;
    float4 p = reinterpret_cast<const float4*>(g_pool)[g * 32 + lane];
    float c = fmaxf(g_cnt[g], 1.0f);
#pragma unroll
    for (int o = 0; o < 10; o++) {
        float4 w = reinterpret_cast<const float4*>(Wg)[o * 32 + lane];
        float s = p.x * w.x + p.y * w.y + p.z * w.z + p.w * w.w;
#pragma unroll
        for (int off = 16; off; off >>= 1) s += __shfl_xor_sync(0xffffffffu, s, off);
        if (lane == 0) out[g * 10 + o] = s / c + bg[o];
    }
}

// ---------------- launch ----------------------------------------------------
extern "C" void kernel_launch(void* const* d_in, const int* in_sizes, int n_in,
                              void* d_out, int out_size) {
    const float* x     = (const float*)d_in[0];
    const int*   ei    = (const int*)d_in[1];      // int32 (JAX x64 disabled)
    const int*   batch = (const int*)d_in[2];
    const float* W0 = (const float*)d_in[3];
    const float* b0 = (const float*)d_in[4];
    const float* W1 = (const float*)d_in[5];
    const float* b1 = (const float*)d_in[6];
    const float* W2 = (const float*)d_in[7];
    const float* b2 = (const float*)d_in[8];
    const float* Wg = (const float*)d_in[9];
    const float* bg = (const float*)d_in[10];
    float* out = (float*)d_out;

    const int N = in_sizes[0] / DH;     // 100000
    const int E = in_sizes[1] / 2;      // 1600000

    const int layer_grid = (N + 127) / 128;
    const int n4 = N * (DH / 4);

    // raise dynamic smem limit (idempotent host-side calls; no static guards)
    cudaFuncSetAttribute(layer_kernel<true, false>,
                         cudaFuncAttributeMaxDynamicSharedMemorySize, LK_SMEM_BYTES);
    cudaFuncSetAttribute(layer_kernel<false, true>,
                         cudaFuncAttributeMaxDynamicSharedMemorySize, LK_SMEM_BYTES);

    __half* x16; cudaGetSymbolAddress((void**)&x16, g_x16);
    __half* hA;  cudaGetSymbolAddress((void**)&hA, g_hA);
    __half* hB;  cudaGetSymbolAddress((void**)&hB, g_hB);

    // CSR build + init + x conversion
    init_kernel<<<(NGRAPH * DH > N ? NGRAPH * DH : N) / 512 + 1, 512>>>(N);
    hist_count_kernel<<<(E + 511) / 512, 512>>>(ei, batch, E, N);
    scan_kernel<<<1, 1024>>>(N);
    fill_kernel<<<(E + 511) / 512, 512>>>(ei, E);
    convert_x_kernel<<<(n4 + 511) / 512, 512>>>(reinterpret_cast<const float4*>(x), n4);

    // fused gather+GEMM layers (double-buffered: no src/dst aliasing)
    layer_kernel<true, false><<<layer_grid, 256, LK_SMEM_BYTES>>>(x16, hA, W0, b0, nullptr, N);
    layer_kernel<true, false><<<layer_grid, 256, LK_SMEM_BYTES>>>(hA, hB, W1, b1, nullptr, N);
    layer_kernel<false, true><<<layer_grid, 256, LK_SMEM_BYTES>>>(hB, nullptr, W2, b2, batch, N);

    final_kernel<<<NGRAPH, 32>>>(Wg, bg, out);
}

// round 13
// speedup vs baseline: 1.7849x; 1.7849x over previous
#include <cuda_runtime.h>
#include <cuda_fp16.h>
#include <cstdint>

#define NNODES_MAX 100000
#define EDGES_MAX  1600000
#define DH 128
#define NGRAPH 512

// hgemm smem: As[128][136] + Ws[128][136] halfs (stride 136 -> conflict-free)
#define HG_STRIDE 136
#define HG_SMEM_BYTES (2 * 128 * HG_STRIDE * 2)

// ---------------- scratch (static device globals; no allocation) ------------
__device__ __half g_x16[NNODES_MAX * DH];    // input features, fp16
__device__ __half g_h16[NNODES_MAX * DH];    // layer output h, fp16
__device__ __half g_agg16[NNODES_MAX * DH];  // h + A*h, fp16
__device__ __half g_w16[3 * DH * DH];        // W0,W1,W2 in fp16
__device__ float  g_pool[NGRAPH * DH];       // per-graph sums (zeroed by final)
__device__ float  g_cnt[NGRAPH];             // per-graph counts (zeroed by final)
__device__ int    g_deg[NNODES_MAX];         // zeroed by scan after use
__device__ int    g_cur[NNODES_MAX];
__device__ int    g_rowptr[NNODES_MAX + 1];
__device__ int    g_col[EDGES_MAX];

// ---------------- helpers ---------------------------------------------------
__device__ __forceinline__ void red2(float* p, float a, float b) {
    asm volatile("red.global.add.v2.f32 [%0], {%1,%2};"
                 :: "l"(p), "f"(a), "f"(b) : "memory");
}
__device__ __forceinline__ float4 h4_to_f4(uint2 u) {
    float2 fa = __half22float2(*reinterpret_cast<__half2*>(&u.x));
    float2 fb = __half22float2(*reinterpret_cast<__half2*>(&u.y));
    return make_float4(fa.x, fa.y, fb.x, fb.y);
}

// ---------------- fused preamble: hist + graph-count + x convert -------------
// g_deg/g_cnt are zero on entry (BSS at load; restored by scan/final each run)
__global__ void hist_convert_kernel(const int* __restrict__ ei,
                                    const int* __restrict__ batch,
                                    const float4* __restrict__ x,
                                    int E, int N, int n4) {
    int i = blockIdx.x * blockDim.x + threadIdx.x;
    if (i < E) atomicAdd(&g_deg[ei[E + i]], 1);   // dst degree
    if (i < N) atomicAdd(&g_cnt[batch[i]], 1.0f);
    if (i < n4) {
        float4 v = x[i];
        __half2* dst = reinterpret_cast<__half2*>(g_x16);
        dst[i * 2]     = __floats2half2_rn(v.x, v.y);
        dst[i * 2 + 1] = __floats2half2_rn(v.z, v.w);
    }
}

// single-block exclusive scan of g_deg into g_rowptr; seeds g_cur; re-zeros deg
__global__ void scan_kernel(int n) {
    const int T = 1024;
    __shared__ int part[T];
    int t = threadIdx.x;
    int C = (n + T - 1) / T;
    int beg = t * C;
    int end = beg + C < n ? beg + C : n;
    int s = 0;
    for (int i = beg; i < end; i++) s += g_deg[i];
    part[t] = s;
    __syncthreads();
    for (int off = 1; off < T; off <<= 1) {
        int v = (t >= off) ? part[t - off] : 0;
        __syncthreads();
        part[t] += v;
        __syncthreads();
    }
    int run = (t == 0) ? 0 : part[t - 1];
    for (int i = beg; i < end; i++) {
        g_rowptr[i] = run;
        g_cur[i]    = run;
        run += g_deg[i];
        g_deg[i] = 0;                 // restore for next launch
    }
    if (t == 0) g_rowptr[n] = part[T - 1];
}

__global__ void fill_kernel(const int* __restrict__ ei, int E) {
    int i = blockIdx.x * blockDim.x + threadIdx.x;
    if (i >= E) return;
    int s = ei[i];
    int d = ei[E + i];
    int pos = atomicAdd(&g_cur[d], 1);
    g_col[pos] = s;
}

__global__ void convert_w_kernel(const float4* __restrict__ w, int layer) {
    int i = blockIdx.x * blockDim.x + threadIdx.x;
    const int n4 = DH * DH / 4;   // 4096
    if (i >= n4) return;
    float4 v = w[i];
    __half2* dst = reinterpret_cast<__half2*>(&g_w16[layer * DH * DH]);
    dst[i * 2]     = __floats2half2_rn(v.x, v.y);
    dst[i * 2 + 1] = __floats2half2_rn(v.z, v.w);
}

// ---------------- gather (R7-proven): agg16[n] = src[n] + sum src[j] ---------
// one warp per node; lane handles 4 halfs (uint2, 8B); serial shfl loop
__global__ void gather16_kernel(const __half* __restrict__ srcp, int N) {
    int w    = (blockIdx.x * blockDim.x + threadIdx.x) >> 5;
    int lane = threadIdx.x & 31;
    if (w >= N) return;
    const uint2* __restrict__ src = reinterpret_cast<const uint2*>(srcp);
    const int beg = g_rowptr[w];
    const int end = g_rowptr[w + 1];

    float4 acc = h4_to_f4(src[w * 32 + lane]);     // seed: own features
    for (int base = beg; base < end; base += 32) {
        int idx = (base + lane < end) ? g_col[base + lane] : 0;
        int cnt = end - base; if (cnt > 32) cnt = 32;
#pragma unroll 4
        for (int j = 0; j < cnt; j++) {
            int s = __shfl_sync(0xffffffffu, idx, j);
            float4 v = h4_to_f4(src[s * 32 + lane]);
            acc.x += v.x; acc.y += v.y; acc.z += v.z; acc.w += v.w;
        }
    }
    uint2 o;
    *reinterpret_cast<__half2*>(&o.x) = __floats2half2_rn(acc.x, acc.y);
    *reinterpret_cast<__half2*>(&o.y) = __floats2half2_rn(acc.z, acc.w);
    reinterpret_cast<uint2*>(g_agg16)[w * 32 + lane] = o;
}

// ---------------- tensor-core GEMM: C = act( agg16 @ W^T + b ) ---------------
// Full-tile cp.async prefetch (A and W, 32KB each), then 8 k-steps of
// ldmatrix+mma (R8-validated mappings). 8 warps, warp = m64 x n32.
template<bool RELU, bool POOL>
__global__ __launch_bounds__(256)
void hgemm_kernel(const __half* __restrict__ Wh, const float* __restrict__ bias,
                  const int* __restrict__ batch, int M) {
    extern __shared__ __half smem[];
    __half* As = smem;                     // [128][HG_STRIDE]
    __half* Ws = smem + 128 * HG_STRIDE;   // [128][HG_STRIDE]

    const int tid  = threadIdx.x;
    const int wid  = tid >> 5;
    const int lane = tid & 31;
    const int rowBase = blockIdx.x * 128;

    // ---- prefetch both full tiles via cp.async (8 x 16B per thread each) ----
    const uint32_t as_base = (uint32_t)__cvta_generic_to_shared(As);
    const uint32_t ws_base = (uint32_t)__cvta_generic_to_shared(Ws);
#pragma unroll
    for (int t = 0; t < 8; t++) {
        int c   = tid + t * 256;          // 0..2047 chunks of 16B
        int row = c >> 4;
        int off = (c & 15) * 8;           // halfs
        int grow = rowBase + row;
        if (grow >= M) grow = M - 1;
        uint32_t da = as_base + (row * HG_STRIDE + off) * 2;
        const __half* ga = &g_agg16[grow * DH + off];
        asm volatile("cp.async.cg.shared.global [%0], [%1], 16;"
                     :: "r"(da), "l"(ga) : "memory");
        uint32_t dw = ws_base + (row * HG_STRIDE + off) * 2;
        const __half* gw = &Wh[row * DH + off];
        asm volatile("cp.async.cg.shared.global [%0], [%1], 16;"
                     :: "r"(dw), "l"(gw) : "memory");
    }
    asm volatile("cp.async.commit_group;" ::: "memory");

    const int g    = lane >> 2;
    const int c2   = (lane & 3) * 2;
    const int mrow = (wid & 1) * 64;
    const int ncol = (wid >> 1) * 32;

    float acc[4][4][4];
#pragma unroll
    for (int mt = 0; mt < 4; mt++)
#pragma unroll
        for (int nt = 0; nt < 4; nt++)
#pragma unroll
            for (int q = 0; q < 4; q++) acc[mt][nt][q] = 0.f;

    asm volatile("cp.async.wait_group 0;" ::: "memory");
    __syncthreads();

    // ---- mainloop: 8 k-steps ----
#pragma unroll
    for (int kk = 0; kk < 8; kk++) {
        const int k0 = kk * 16;
        uint32_t af[4][4], bf[4][2];
#pragma unroll
        for (int mt = 0; mt < 4; mt++) {
            uint32_t aaddr = (uint32_t)__cvta_generic_to_shared(
                &As[(mrow + mt * 16 + (lane & 15)) * HG_STRIDE + k0 + ((lane >> 4) << 3)]);
            asm volatile(
                "ldmatrix.sync.aligned.m8n8.x4.shared.b16 {%0,%1,%2,%3}, [%4];"
                : "=r"(af[mt][0]), "=r"(af[mt][1]),
                  "=r"(af[mt][2]), "=r"(af[mt][3])
                : "r"(aaddr));
        }
#pragma unroll
        for (int nt = 0; nt < 4; nt++) {
            uint32_t baddr = (uint32_t)__cvta_generic_to_shared(
                &Ws[(ncol + nt * 8 + (lane & 7)) * HG_STRIDE + k0 + (((lane >> 3) & 1) << 3)]);
            asm volatile(
                "ldmatrix.sync.aligned.m8n8.x2.shared.b16 {%0,%1}, [%2];"
                : "=r"(bf[nt][0]), "=r"(bf[nt][1])
                : "r"(baddr));
        }
#pragma unroll
        for (int mt = 0; mt < 4; mt++)
#pragma unroll
            for (int nt = 0; nt < 4; nt++) {
                asm volatile(
                    "mma.sync.aligned.m16n8k16.row.col.f32.f16.f16.f32 "
                    "{%0,%1,%2,%3}, {%4,%5,%6,%7}, {%8,%9}, {%0,%1,%2,%3};"
                    : "+f"(acc[mt][nt][0]), "+f"(acc[mt][nt][1]),
                      "+f"(acc[mt][nt][2]), "+f"(acc[mt][nt][3])
                    : "r"(af[mt][0]), "r"(af[mt][1]), "r"(af[mt][2]), "r"(af[mt][3]),
                      "r"(bf[nt][0]), "r"(bf[nt][1]));
            }
    }

    // ---- epilogue ----
#pragma unroll
    for (int nt = 0; nt < 4; nt++) {
        int col = ncol + nt * 8 + c2;
        float2 bb = *reinterpret_cast<const float2*>(&bias[col]);
#pragma unroll
        for (int mt = 0; mt < 4; mt++) {
            int row0 = rowBase + mrow + mt * 16 + g;
            int row1 = row0 + 8;
            float c0 = acc[mt][nt][0] + bb.x;
            float c1 = acc[mt][nt][1] + bb.y;
            float c2v = acc[mt][nt][2] + bb.x;
            float c3 = acc[mt][nt][3] + bb.y;
            if (RELU) {
                c0 = fmaxf(c0, 0.f); c1 = fmaxf(c1, 0.f);
                c2v = fmaxf(c2v, 0.f); c3 = fmaxf(c3, 0.f);
            }
            if (POOL) {
                if (row0 < M) red2(&g_pool[batch[row0] * DH + col], c0, c1);
                if (row1 < M) red2(&g_pool[batch[row1] * DH + col], c2v, c3);
            } else {
                if (row0 < M)
                    *reinterpret_cast<__half2*>(&g_h16[row0 * DH + col]) =
                        __floats2half2_rn(c0, c1);
                if (row1 < M)
                    *reinterpret_cast<__half2*>(&g_h16[row1 * DH + col]) =
                        __floats2half2_rn(c2v, c3);
            }
        }
    }
}

// ---------------- head; also restores pool/cnt to zero for next launch -------
__global__ void final_kernel(const float* __restrict__ Wg,
                             const float* __restrict__ bg,
                             float* __restrict__ out) {
    int g = blockIdx.x;
    int lane = threadIdx.x;
    float4 p = reinterpret_cast<const float4*>(g_pool)[g * 32 + lane];
    float c = fmaxf(g_cnt[g], 1.0f);
#pragma unroll
    for (int o = 0; o < 10; o++) {
        float4 w = reinterpret_cast<const float4*>(Wg)[o * 32 + lane];
        float s = p.x * w.x + p.y * w.y + p.z * w.z + p.w * w.w;
#pragma unroll
        for (int off = 16; off; off >>= 1) s += __shfl_xor_sync(0xffffffffu, s, off);
        if (lane == 0) out[g * 10 + o] = s / c + bg[o];
    }
    // restore zeros (deterministic per-launch state)
    reinterpret_cast<float4*>(g_pool)[g * 32 + lane] = make_float4(0.f, 0.f, 0.f, 0.f);
    if (lane == 0) g_cnt[g] = 0.f;
}

// ---------------- launch ----------------------------------------------------
extern "C" void kernel_launch(void* const* d_in, const int* in_sizes, int n_in,
                              void* d_out, int out_size) {
    const float* x     = (const float*)d_in[0];
    const int*   ei    = (const int*)d_in[1];      // int32 (JAX x64 disabled)
    const int*   batch = (const int*)d_in[2];
    const float* W0 = (const float*)d_in[3];
    const float* b0 = (const float*)d_in[4];
    const float* W1 = (const float*)d_in[5];
    const float* b1 = (const float*)d_in[6];
    const float* W2 = (const float*)d_in[7];
    const float* b2 = (const float*)d_in[8];
    const float* Wg = (const float*)d_in[9];
    const float* bg = (const float*)d_in[10];
    float* out = (float*)d_out;

    const int N = in_sizes[0] / DH;     // 100000
    const int E = in_sizes[1] / 2;      // 1600000

    const int gemm_grid = (N + 127) / 128;
    const int gat_grid  = (N + 7) / 8;  // 8 warps/block, 1 node/warp
    const int n4 = N * (DH / 4);

    cudaFuncSetAttribute(hgemm_kernel<true, false>,
                         cudaFuncAttributeMaxDynamicSharedMemorySize, HG_SMEM_BYTES);
    cudaFuncSetAttribute(hgemm_kernel<false, true>,
                         cudaFuncAttributeMaxDynamicSharedMemorySize, HG_SMEM_BYTES);

    __half* w16; cudaGetSymbolAddress((void**)&w16, g_w16);
    __half* x16; cudaGetSymbolAddress((void**)&x16, g_x16);
    __half* h16; cudaGetSymbolAddress((void**)&h16, g_h16);

    // CSR build + conversions (deg/cnt/pool are zero on entry; restored below)
    hist_convert_kernel<<<(n4 + 511) / 512, 512>>>(
        ei, batch, reinterpret_cast<const float4*>(x), E, N, n4);
    scan_kernel<<<1, 1024>>>(N);
    fill_kernel<<<(E + 511) / 512, 512>>>(ei, E);
    convert_w_kernel<<<8, 512>>>(reinterpret_cast<const float4*>(W0), 0);
    convert_w_kernel<<<8, 512>>>(reinterpret_cast<const float4*>(W1), 1);
    convert_w_kernel<<<8, 512>>>(reinterpret_cast<const float4*>(W2), 2);

    // layer 0
    gather16_kernel<<<gat_grid, 256>>>(x16, N);
    hgemm_kernel<true, false><<<gemm_grid, 256, HG_SMEM_BYTES>>>(w16, b0, nullptr, N);
    // layer 1
    gather16_kernel<<<gat_grid, 256>>>(h16, N);
    hgemm_kernel<true, false><<<gemm_grid, 256, HG_SMEM_BYTES>>>(w16 + DH * DH, b1, nullptr, N);
    // layer 2 + fused pooling
    gather16_kernel<<<gat_grid, 256>>>(h16, N);
    hgemm_kernel<false, true><<<gemm_grid, 256, HG_SMEM_BYTES>>>(w16 + 2 * DH * DH, b2, batch, N);

    final_kernel<<<NGRAPH, 32>>>(Wg, bg, out);
}